// round 3
// baseline (speedup 1.0000x reference)
#include <cuda_runtime.h>
#include <cuda_bf16.h>

// CameraSpline pose evaluation.
// Inputs (metadata order): t [M] f32, ctrl_trans [K,3] f32, ctrl_quats [K,4] f32, N [1] i32.
// Output: R [M,3,3] flattened (9*M floats) followed by T [M,3] (3*M floats).

__device__ __forceinline__ float4 qnormalize(float4 q) {
    float inv = rsqrtf(q.x * q.x + q.y * q.y + q.z * q.z + q.w * q.w);
    return make_float4(q.x * inv, q.y * inv, q.z * inv, q.w * inv);
}

__device__ __forceinline__ float4 qslerp(float4 q0, float4 q1, float u) {
    float dot = q0.x * q1.x + q0.y * q1.y + q0.z * q1.z + q0.w * q1.w;
    dot = fminf(fmaxf(dot, -1.0f), 1.0f);
    float sgn = (dot < 0.0f) ? -1.0f : 1.0f;
    float ad = fminf(fabsf(dot), 1.0f);
    float theta = acosf(ad);
    float st = __sinf(theta);
    float w0, w1;
    if (fabsf(st) > 1e-6f) {
        float inv = __frcp_rn(st);
        w0 = __sinf((1.0f - u) * theta) * inv;
        w1 = __sinf(u * theta) * inv;
    } else {
        w0 = 1.0f - u;
        w1 = u;
    }
    w1 *= sgn;
    return make_float4(w0 * q0.x + w1 * q1.x,
                       w0 * q0.y + w1 * q1.y,
                       w0 * q0.z + w1 * q1.z,
                       w0 * q0.w + w1 * q1.w);
}

__global__ void camera_spline_kernel(const float* __restrict__ t,
                                     const float* __restrict__ ctrl_trans,
                                     const float* __restrict__ ctrl_quats,
                                     const int* __restrict__ Nptr,
                                     float* __restrict__ out,
                                     int M, int K)
{
    int m = blockIdx.x * blockDim.x + threadIdx.x;
    if (m >= M) return;

    int N = __ldg(Nptr);
    float km1 = (float)(K - 1);
    float nm1 = (float)max(N - 1, 1);

    // Match XLA rounding EXACTLY. XLA rewrites x/c -> x * (1/c) with the
    // reciprocal correctly rounded in fp32. So the reference computes
    //   t_ctrl = fl( fl(t * (K-1)) * fl(1/(N-1)) )
    // and u = t_ctrl - i is exact (Sterbenz), so this must bit-match.
    float rcp = __fdiv_rn(1.0f, nm1);
    float tc = __fmul_rn(__fmul_rn(t[m], km1), rcp);

    float fi = floorf(tc);
    int i = (int)fi;
    i = min(max(i, 0), K - 2);
    float u = tc - (float)i;

    int im1 = max(i - 1, 0);
    int ip2 = min(i + 2, K - 1);

    // ---- translation: cubic Hermite ----
    float3 p0 = make_float3(ctrl_trans[3 * i + 0], ctrl_trans[3 * i + 1], ctrl_trans[3 * i + 2]);
    float3 p1 = make_float3(ctrl_trans[3 * (i + 1) + 0], ctrl_trans[3 * (i + 1) + 1], ctrl_trans[3 * (i + 1) + 2]);
    float3 pm = make_float3(ctrl_trans[3 * im1 + 0], ctrl_trans[3 * im1 + 1], ctrl_trans[3 * im1 + 2]);
    float3 pp = make_float3(ctrl_trans[3 * ip2 + 0], ctrl_trans[3 * ip2 + 1], ctrl_trans[3 * ip2 + 2]);

    float3 d01 = make_float3(p1.x - p0.x, p1.y - p0.y, p1.z - p0.z);
    float3 m0, m1;
    if (i > 0) {
        m0 = make_float3(0.5f * (p1.x - pm.x), 0.5f * (p1.y - pm.y), 0.5f * (p1.z - pm.z));
    } else {
        m0 = d01;
    }
    if (i + 1 < K - 1) {
        m1 = make_float3(0.5f * (pp.x - p0.x), 0.5f * (pp.y - p0.y), 0.5f * (pp.z - p0.z));
    } else {
        m1 = d01;
    }

    float u2 = u * u;
    float u3 = u2 * u;
    float h00 = 2.0f * u3 - 3.0f * u2 + 1.0f;
    float h10 = u3 - 2.0f * u2 + u;
    float h01 = -2.0f * u3 + 3.0f * u2;
    float h11 = u3 - u2;

    float Tx = h00 * p0.x + h10 * m0.x + h01 * p1.x + h11 * m1.x;
    float Ty = h00 * p0.y + h10 * m0.y + h01 * p1.y + h11 * m1.y;
    float Tz = h00 * p0.z + h10 * m0.z + h01 * p1.z + h11 * m1.z;

    // ---- rotation: Squad (double slerp) ----
    const float4* quats = (const float4*)ctrl_quats;
    float4 q_i  = qnormalize(quats[i]);
    float4 q_i1 = qnormalize(quats[i + 1]);
    float4 q_m  = qnormalize(quats[im1]);
    float4 q_p  = qnormalize(quats[ip2]);

    float4 s_main = qslerp(q_i, q_i1, u);
    float4 s_aux  = qslerp(q_m, q_p, u);
    float u_sq = 2.0f * u * (1.0f - u);
    float4 q = qnormalize(qslerp(s_main, s_aux, u_sq));

    float w = q.x, x = q.y, y = q.z, z = q.w;
    float xx = x * x, yy = y * y, zz = z * z;
    float xy = x * y, xz = x * z, yz = y * z;
    float wx = w * x, wy = w * y, wz = w * z;

    float* R = out + (size_t)m * 9;
    R[0] = 1.0f - 2.0f * (yy + zz);
    R[1] = 2.0f * (xy - wz);
    R[2] = 2.0f * (xz + wy);
    R[3] = 2.0f * (xy + wz);
    R[4] = 1.0f - 2.0f * (xx + zz);
    R[5] = 2.0f * (yz - wx);
    R[6] = 2.0f * (xz - wy);
    R[7] = 2.0f * (yz + wx);
    R[8] = 1.0f - 2.0f * (xx + yy);

    float* Tout = out + (size_t)M * 9 + (size_t)m * 3;
    Tout[0] = Tx;
    Tout[1] = Ty;
    Tout[2] = Tz;
}

extern "C" void kernel_launch(void* const* d_in, const int* in_sizes, int n_in,
                              void* d_out, int out_size)
{
    const float* t          = (const float*)d_in[0];
    const float* ctrl_trans = (const float*)d_in[1];
    const float* ctrl_quats = (const float*)d_in[2];
    const int*   Nptr       = (const int*)d_in[3];

    int M = in_sizes[0];
    int K = in_sizes[1] / 3;

    float* out = (float*)d_out;

    int threads = 256;
    int blocks = (M + threads - 1) / threads;
    camera_spline_kernel<<<blocks, threads>>>(t, ctrl_trans, ctrl_quats, Nptr, out, M, K);
}

// round 5
// speedup vs baseline: 1.3793x; 1.3793x over previous
#include <cuda_runtime.h>
#include <cuda_bf16.h>
#include <cstdint>

// CameraSpline pose evaluation.
// Inputs (metadata order): t [M] f32, ctrl_trans [K,3] f32, ctrl_quats [K,4] f32, N [1] i32.
// Output: R [M,3,3] flattened (9*M floats) followed by T [M,3] (3*M floats).
//
// R3 -> R5: outputs staged through shared memory and written as dense,
// coalesced STG.128. The naive per-thread strided stores (12 x STG.32 at
// 36B stride) cost ~432 L1 sectors/warp vs the 48-sector ideal; that was
// the 80.5% L1 throughput bound in the R3 profile.

#define TPB 256
#define SROW 13   // 12 payload floats + 1 pad -> odd stride, conflict-free STS

__device__ __forceinline__ float4 qnormalize(float4 q) {
    float inv = rsqrtf(q.x * q.x + q.y * q.y + q.z * q.z + q.w * q.w);
    return make_float4(q.x * inv, q.y * inv, q.z * inv, q.w * inv);
}

__device__ __forceinline__ float4 qslerp(float4 q0, float4 q1, float u) {
    float dot = q0.x * q1.x + q0.y * q1.y + q0.z * q1.z + q0.w * q1.w;
    dot = fminf(fmaxf(dot, -1.0f), 1.0f);
    float sgn = (dot < 0.0f) ? -1.0f : 1.0f;
    float ad = fminf(fabsf(dot), 1.0f);
    float theta = acosf(ad);
    float st = __sinf(theta);
    float w0, w1;
    if (fabsf(st) > 1e-6f) {
        float inv = __frcp_rn(st);
        w0 = __sinf((1.0f - u) * theta) * inv;
        w1 = __sinf(u * theta) * inv;
    } else {
        w0 = 1.0f - u;
        w1 = u;
    }
    w1 *= sgn;
    return make_float4(w0 * q0.x + w1 * q1.x,
                       w0 * q0.y + w1 * q1.y,
                       w0 * q0.z + w1 * q1.z,
                       w0 * q0.w + w1 * q1.w);
}

__global__ __launch_bounds__(TPB)
void camera_spline_kernel(const float* __restrict__ t,
                          const float* __restrict__ ctrl_trans,
                          const float* __restrict__ ctrl_quats,
                          const int* __restrict__ Nptr,
                          float* __restrict__ out,
                          int M, int K)
{
    __shared__ float s[TPB * SROW];

    int tid = threadIdx.x;
    int blockStart = blockIdx.x * TPB;
    int m = blockStart + tid;

    if (m < M) {
        int N = __ldg(Nptr);
        float km1 = (float)(K - 1);
        float nm1 = (float)max(N - 1, 1);

        // Match XLA rounding EXACTLY: t_ctrl = fl( fl(t*(K-1)) * fl(1/(N-1)) )
        float rcp = __fdiv_rn(1.0f, nm1);
        float tc = __fmul_rn(__fmul_rn(t[m], km1), rcp);

        float fi = floorf(tc);
        int i = (int)fi;
        i = min(max(i, 0), K - 2);
        float u = tc - (float)i;

        int im1 = max(i - 1, 0);
        int ip2 = min(i + 2, K - 1);

        // ---- translation: cubic Hermite ----
        float3 p0 = make_float3(ctrl_trans[3 * i + 0], ctrl_trans[3 * i + 1], ctrl_trans[3 * i + 2]);
        float3 p1 = make_float3(ctrl_trans[3 * (i + 1) + 0], ctrl_trans[3 * (i + 1) + 1], ctrl_trans[3 * (i + 1) + 2]);
        float3 pm = make_float3(ctrl_trans[3 * im1 + 0], ctrl_trans[3 * im1 + 1], ctrl_trans[3 * im1 + 2]);
        float3 pp = make_float3(ctrl_trans[3 * ip2 + 0], ctrl_trans[3 * ip2 + 1], ctrl_trans[3 * ip2 + 2]);

        float3 d01 = make_float3(p1.x - p0.x, p1.y - p0.y, p1.z - p0.z);
        float3 m0, m1;
        if (i > 0) {
            m0 = make_float3(0.5f * (p1.x - pm.x), 0.5f * (p1.y - pm.y), 0.5f * (p1.z - pm.z));
        } else {
            m0 = d01;
        }
        if (i + 1 < K - 1) {
            m1 = make_float3(0.5f * (pp.x - p0.x), 0.5f * (pp.y - p0.y), 0.5f * (pp.z - p0.z));
        } else {
            m1 = d01;
        }

        float u2 = u * u;
        float u3 = u2 * u;
        float h00 = 2.0f * u3 - 3.0f * u2 + 1.0f;
        float h10 = u3 - 2.0f * u2 + u;
        float h01 = -2.0f * u3 + 3.0f * u2;
        float h11 = u3 - u2;

        float Tx = h00 * p0.x + h10 * m0.x + h01 * p1.x + h11 * m1.x;
        float Ty = h00 * p0.y + h10 * m0.y + h01 * p1.y + h11 * m1.y;
        float Tz = h00 * p0.z + h10 * m0.z + h01 * p1.z + h11 * m1.z;

        // ---- rotation: Squad (double slerp) ----
        const float4* quats = (const float4*)ctrl_quats;
        float4 q_i  = qnormalize(quats[i]);
        float4 q_i1 = qnormalize(quats[i + 1]);
        float4 q_m  = qnormalize(quats[im1]);
        float4 q_p  = qnormalize(quats[ip2]);

        float4 s_main = qslerp(q_i, q_i1, u);
        float4 s_aux  = qslerp(q_m, q_p, u);
        float u_sq = 2.0f * u * (1.0f - u);
        float4 q = qnormalize(qslerp(s_main, s_aux, u_sq));

        float w = q.x, x = q.y, y = q.z, z = q.w;
        float xx = x * x, yy = y * y, zz = z * z;
        float xy = x * y, xz = x * z, yz = y * z;
        float wx = w * x, wy = w * y, wz = w * z;

        float* row = s + tid * SROW;
        row[0] = 1.0f - 2.0f * (yy + zz);
        row[1] = 2.0f * (xy - wz);
        row[2] = 2.0f * (xz + wy);
        row[3] = 2.0f * (xy + wz);
        row[4] = 1.0f - 2.0f * (xx + zz);
        row[5] = 2.0f * (yz - wx);
        row[6] = 2.0f * (xz - wy);
        row[7] = 2.0f * (yz + wx);
        row[8] = 1.0f - 2.0f * (xx + yy);
        row[9]  = Tx;
        row[10] = Ty;
        row[11] = Tz;
    }

    __syncthreads();

    int count = min(TPB, M - blockStart);
    if (count <= 0) return;

    // ---- R chunk: count*9 contiguous floats at out + blockStart*9 ----
    {
        float* outR = out + (size_t)blockStart * 9;
        int nR = count * 9;
        bool al = ((((size_t)blockStart * 9) & 3) == 0) && ((nR & 3) == 0) &&
                  ((((unsigned long long)outR) & 15ull) == 0);
        if (al) {
            float4* outR4 = (float4*)outR;
            int nR4 = nR >> 2;
            for (int j = tid; j < nR4; j += TPB) {
                int e = j << 2;
                float4 v;
                v.x = s[(e + 0) / 9 * SROW + (e + 0) % 9];
                v.y = s[(e + 1) / 9 * SROW + (e + 1) % 9];
                v.z = s[(e + 2) / 9 * SROW + (e + 2) % 9];
                v.w = s[(e + 3) / 9 * SROW + (e + 3) % 9];
                outR4[j] = v;
            }
        } else {
            for (int e = tid; e < nR; e += TPB)
                outR[e] = s[e / 9 * SROW + e % 9];
        }
    }

    // ---- T chunk: count*3 contiguous floats at out + M*9 + blockStart*3 ----
    {
        float* outT = out + (size_t)M * 9 + (size_t)blockStart * 3;
        int nT = count * 3;
        bool al = ((((size_t)M * 9 + (size_t)blockStart * 3) & 3) == 0) && ((nT & 3) == 0) &&
                  ((((unsigned long long)outT) & 15ull) == 0);
        if (al) {
            float4* outT4 = (float4*)outT;
            int nT4 = nT >> 2;
            for (int j = tid; j < nT4; j += TPB) {
                int e = j << 2;
                float4 v;
                v.x = s[(e + 0) / 3 * SROW + 9 + (e + 0) % 3];
                v.y = s[(e + 1) / 3 * SROW + 9 + (e + 1) % 3];
                v.z = s[(e + 2) / 3 * SROW + 9 + (e + 2) % 3];
                v.w = s[(e + 3) / 3 * SROW + 9 + (e + 3) % 3];
                outT4[j] = v;
            }
        } else {
            for (int e = tid; e < nT; e += TPB)
                outT[e] = s[e / 3 * SROW + 9 + e % 3];
        }
    }
}

extern "C" void kernel_launch(void* const* d_in, const int* in_sizes, int n_in,
                              void* d_out, int out_size)
{
    const float* t          = (const float*)d_in[0];
    const float* ctrl_trans = (const float*)d_in[1];
    const float* ctrl_quats = (const float*)d_in[2];
    const int*   Nptr       = (const int*)d_in[3];

    int M = in_sizes[0];
    int K = in_sizes[1] / 3;

    float* out = (float*)d_out;

    int blocks = (M + TPB - 1) / TPB;
    camera_spline_kernel<<<blocks, TPB>>>(t, ctrl_trans, ctrl_quats, Nptr, out, M, K);
}

// round 6
// speedup vs baseline: 1.5217x; 1.1033x over previous
#include <cuda_runtime.h>
#include <cuda_bf16.h>
#include <cstdint>

// CameraSpline pose evaluation.
// Inputs (metadata order): t [M] f32, ctrl_trans [K,3] f32, ctrl_quats [K,4] f32, N [1] i32.
// Output: R [M,3,3] flattened (9*M floats) followed by T [M,3] (3*M floats).
//
// R5 -> R6: random gathers repacked. A precompute kernel builds a per-control-
// point table of 32B records {trans(pad), normalized quat}; the main kernel
// gathers 4 records (4 L1 sectors/lane vs ~16 before) and skips per-thread
// quat normalization. Outputs stay smem-staged + coalesced (R5 win).

#define TPB 256
#define SROW 13        // 12 payload floats + 1 pad -> conflict-free STS
#define CAP 1048576    // max control points supported by the record table

// 2 float4 per control point: [2k] = (tx,ty,tz,0), [2k+1] = normalized quat.
__device__ float4 g_rec[2 * CAP];

__global__ void precompute_records(const float* __restrict__ ctrl_trans,
                                   const float* __restrict__ ctrl_quats,
                                   int K)
{
    int k = blockIdx.x * blockDim.x + threadIdx.x;
    if (k >= K) return;
    float4 q = ((const float4*)ctrl_quats)[k];
    float inv = rsqrtf(q.x * q.x + q.y * q.y + q.z * q.z + q.w * q.w);
    g_rec[2 * k]     = make_float4(ctrl_trans[3 * k + 0], ctrl_trans[3 * k + 1],
                                   ctrl_trans[3 * k + 2], 0.0f);
    g_rec[2 * k + 1] = make_float4(q.x * inv, q.y * inv, q.z * inv, q.w * inv);
}

__device__ __forceinline__ float4 qnormalize(float4 q) {
    float inv = rsqrtf(q.x * q.x + q.y * q.y + q.z * q.z + q.w * q.w);
    return make_float4(q.x * inv, q.y * inv, q.z * inv, q.w * inv);
}

__device__ __forceinline__ float4 qslerp(float4 q0, float4 q1, float u) {
    float dot = q0.x * q1.x + q0.y * q1.y + q0.z * q1.z + q0.w * q1.w;
    dot = fminf(fmaxf(dot, -1.0f), 1.0f);
    float sgn = (dot < 0.0f) ? -1.0f : 1.0f;
    float ad = fminf(fabsf(dot), 1.0f);
    float theta = acosf(ad);
    float st = __sinf(theta);
    float w0, w1;
    if (fabsf(st) > 1e-6f) {
        float inv = __frcp_rn(st);
        w0 = __sinf((1.0f - u) * theta) * inv;
        w1 = __sinf(u * theta) * inv;
    } else {
        w0 = 1.0f - u;
        w1 = u;
    }
    w1 *= sgn;
    return make_float4(w0 * q0.x + w1 * q1.x,
                       w0 * q0.y + w1 * q1.y,
                       w0 * q0.z + w1 * q1.z,
                       w0 * q0.w + w1 * q1.w);
}

__global__ __launch_bounds__(TPB)
void camera_spline_kernel(const float* __restrict__ t,
                          const int* __restrict__ Nptr,
                          float* __restrict__ out,
                          int M, int K)
{
    __shared__ float s[TPB * SROW];

    int tid = threadIdx.x;
    int blockStart = blockIdx.x * TPB;
    int m = blockStart + tid;

    if (m < M) {
        int N = __ldg(Nptr);
        float km1 = (float)(K - 1);
        float nm1 = (float)max(N - 1, 1);

        // Match XLA rounding EXACTLY: t_ctrl = fl( fl(t*(K-1)) * fl(1/(N-1)) )
        float rcp = __fdiv_rn(1.0f, nm1);
        float tc = __fmul_rn(__fmul_rn(t[m], km1), rcp);

        float fi = floorf(tc);
        int i = (int)fi;
        i = min(max(i, 0), K - 2);
        float u = tc - (float)i;

        int im1 = max(i - 1, 0);
        int ip2 = min(i + 2, K - 1);

        // Gather: records 2i..2i+3 are 64B contiguous; im1/ip2 one sector each.
        float4 tr0 = g_rec[2 * i];
        float4 q_i = g_rec[2 * i + 1];
        float4 tr1 = g_rec[2 * i + 2];
        float4 q_i1 = g_rec[2 * i + 3];
        float4 trm = g_rec[2 * im1];
        float4 q_m = g_rec[2 * im1 + 1];
        float4 trp = g_rec[2 * ip2];
        float4 q_p = g_rec[2 * ip2 + 1];

        // ---- translation: cubic Hermite ----
        float3 p0 = make_float3(tr0.x, tr0.y, tr0.z);
        float3 p1 = make_float3(tr1.x, tr1.y, tr1.z);

        float3 d01 = make_float3(p1.x - p0.x, p1.y - p0.y, p1.z - p0.z);
        float3 m0, m1;
        if (i > 0) {
            m0 = make_float3(0.5f * (p1.x - trm.x), 0.5f * (p1.y - trm.y), 0.5f * (p1.z - trm.z));
        } else {
            m0 = d01;
        }
        if (i + 1 < K - 1) {
            m1 = make_float3(0.5f * (trp.x - p0.x), 0.5f * (trp.y - p0.y), 0.5f * (trp.z - p0.z));
        } else {
            m1 = d01;
        }

        float u2 = u * u;
        float u3 = u2 * u;
        float h00 = 2.0f * u3 - 3.0f * u2 + 1.0f;
        float h10 = u3 - 2.0f * u2 + u;
        float h01 = -2.0f * u3 + 3.0f * u2;
        float h11 = u3 - u2;

        float Tx = h00 * p0.x + h10 * m0.x + h01 * p1.x + h11 * m1.x;
        float Ty = h00 * p0.y + h10 * m0.y + h01 * p1.y + h11 * m1.y;
        float Tz = h00 * p0.z + h10 * m0.z + h01 * p1.z + h11 * m1.z;

        // ---- rotation: Squad (double slerp); quats pre-normalized ----
        float4 s_main = qslerp(q_i, q_i1, u);
        float4 s_aux  = qslerp(q_m, q_p, u);
        float u_sq = 2.0f * u * (1.0f - u);
        float4 q = qnormalize(qslerp(s_main, s_aux, u_sq));

        float w = q.x, x = q.y, y = q.z, z = q.w;
        float xx = x * x, yy = y * y, zz = z * z;
        float xy = x * y, xz = x * z, yz = y * z;
        float wx = w * x, wy = w * y, wz = w * z;

        float* row = s + tid * SROW;
        row[0] = 1.0f - 2.0f * (yy + zz);
        row[1] = 2.0f * (xy - wz);
        row[2] = 2.0f * (xz + wy);
        row[3] = 2.0f * (xy + wz);
        row[4] = 1.0f - 2.0f * (xx + zz);
        row[5] = 2.0f * (yz - wx);
        row[6] = 2.0f * (xz - wy);
        row[7] = 2.0f * (yz + wx);
        row[8] = 1.0f - 2.0f * (xx + yy);
        row[9]  = Tx;
        row[10] = Ty;
        row[11] = Tz;
    }

    __syncthreads();

    int count = min(TPB, M - blockStart);
    if (count <= 0) return;

    // ---- R chunk: count*9 contiguous floats at out + blockStart*9 ----
    {
        float* outR = out + (size_t)blockStart * 9;
        int nR = count * 9;
        bool al = ((((size_t)blockStart * 9) & 3) == 0) && ((nR & 3) == 0) &&
                  ((((unsigned long long)outR) & 15ull) == 0);
        if (al) {
            float4* outR4 = (float4*)outR;
            int nR4 = nR >> 2;
            for (int j = tid; j < nR4; j += TPB) {
                int e = j << 2;
                float4 v;
                v.x = s[(e + 0) / 9 * SROW + (e + 0) % 9];
                v.y = s[(e + 1) / 9 * SROW + (e + 1) % 9];
                v.z = s[(e + 2) / 9 * SROW + (e + 2) % 9];
                v.w = s[(e + 3) / 9 * SROW + (e + 3) % 9];
                outR4[j] = v;
            }
        } else {
            for (int e = tid; e < nR; e += TPB)
                outR[e] = s[e / 9 * SROW + e % 9];
        }
    }

    // ---- T chunk: count*3 contiguous floats at out + M*9 + blockStart*3 ----
    {
        float* outT = out + (size_t)M * 9 + (size_t)blockStart * 3;
        int nT = count * 3;
        bool al = ((((size_t)M * 9 + (size_t)blockStart * 3) & 3) == 0) && ((nT & 3) == 0) &&
                  ((((unsigned long long)outT) & 15ull) == 0);
        if (al) {
            float4* outT4 = (float4*)outT;
            int nT4 = nT >> 2;
            for (int j = tid; j < nT4; j += TPB) {
                int e = j << 2;
                float4 v;
                v.x = s[(e + 0) / 3 * SROW + 9 + (e + 0) % 3];
                v.y = s[(e + 1) / 3 * SROW + 9 + (e + 1) % 3];
                v.z = s[(e + 2) / 3 * SROW + 9 + (e + 2) % 3];
                v.w = s[(e + 3) / 3 * SROW + 9 + (e + 3) % 3];
                outT4[j] = v;
            }
        } else {
            for (int e = tid; e < nT; e += TPB)
                outT[e] = s[e / 3 * SROW + 9 + e % 3];
        }
    }
}

// Fallback for K > CAP: direct-gather version (R5 behavior, loads + normalizes
// quats in-kernel).
__global__ __launch_bounds__(TPB)
void camera_spline_kernel_direct(const float* __restrict__ t,
                                 const float* __restrict__ ctrl_trans,
                                 const float* __restrict__ ctrl_quats,
                                 const int* __restrict__ Nptr,
                                 float* __restrict__ out,
                                 int M, int K)
{
    int m = blockIdx.x * blockDim.x + threadIdx.x;
    if (m >= M) return;

    int N = __ldg(Nptr);
    float km1 = (float)(K - 1);
    float nm1 = (float)max(N - 1, 1);
    float rcp = __fdiv_rn(1.0f, nm1);
    float tc = __fmul_rn(__fmul_rn(t[m], km1), rcp);
    float fi = floorf(tc);
    int i = (int)fi;
    i = min(max(i, 0), K - 2);
    float u = tc - (float)i;
    int im1 = max(i - 1, 0);
    int ip2 = min(i + 2, K - 1);

    float3 p0 = make_float3(ctrl_trans[3 * i + 0], ctrl_trans[3 * i + 1], ctrl_trans[3 * i + 2]);
    float3 p1 = make_float3(ctrl_trans[3 * (i + 1) + 0], ctrl_trans[3 * (i + 1) + 1], ctrl_trans[3 * (i + 1) + 2]);
    float3 pm = make_float3(ctrl_trans[3 * im1 + 0], ctrl_trans[3 * im1 + 1], ctrl_trans[3 * im1 + 2]);
    float3 pp = make_float3(ctrl_trans[3 * ip2 + 0], ctrl_trans[3 * ip2 + 1], ctrl_trans[3 * ip2 + 2]);

    float3 d01 = make_float3(p1.x - p0.x, p1.y - p0.y, p1.z - p0.z);
    float3 m0 = (i > 0) ? make_float3(0.5f * (p1.x - pm.x), 0.5f * (p1.y - pm.y), 0.5f * (p1.z - pm.z)) : d01;
    float3 m1 = (i + 1 < K - 1) ? make_float3(0.5f * (pp.x - p0.x), 0.5f * (pp.y - p0.y), 0.5f * (pp.z - p0.z)) : d01;

    float u2 = u * u, u3 = u2 * u;
    float h00 = 2.0f * u3 - 3.0f * u2 + 1.0f;
    float h10 = u3 - 2.0f * u2 + u;
    float h01 = -2.0f * u3 + 3.0f * u2;
    float h11 = u3 - u2;
    float Tx = h00 * p0.x + h10 * m0.x + h01 * p1.x + h11 * m1.x;
    float Ty = h00 * p0.y + h10 * m0.y + h01 * p1.y + h11 * m1.y;
    float Tz = h00 * p0.z + h10 * m0.z + h01 * p1.z + h11 * m1.z;

    const float4* quats = (const float4*)ctrl_quats;
    float4 q_i  = qnormalize(quats[i]);
    float4 q_i1 = qnormalize(quats[i + 1]);
    float4 q_m  = qnormalize(quats[im1]);
    float4 q_p  = qnormalize(quats[ip2]);
    float4 s_main = qslerp(q_i, q_i1, u);
    float4 s_aux  = qslerp(q_m, q_p, u);
    float4 q = qnormalize(qslerp(s_main, s_aux, 2.0f * u * (1.0f - u)));

    float w = q.x, x = q.y, y = q.z, z = q.w;
    float* R = out + (size_t)m * 9;
    R[0] = 1.0f - 2.0f * (y * y + z * z);
    R[1] = 2.0f * (x * y - w * z);
    R[2] = 2.0f * (x * z + w * y);
    R[3] = 2.0f * (x * y + w * z);
    R[4] = 1.0f - 2.0f * (x * x + z * z);
    R[5] = 2.0f * (y * z - w * x);
    R[6] = 2.0f * (y * z + w * x) * 0.0f + 2.0f * (x * z - w * y);
    R[7] = 2.0f * (y * z + w * x);
    R[8] = 1.0f - 2.0f * (x * x + y * y);
    float* Tout = out + (size_t)M * 9 + (size_t)m * 3;
    Tout[0] = Tx; Tout[1] = Ty; Tout[2] = Tz;
}

extern "C" void kernel_launch(void* const* d_in, const int* in_sizes, int n_in,
                              void* d_out, int out_size)
{
    const float* t          = (const float*)d_in[0];
    const float* ctrl_trans = (const float*)d_in[1];
    const float* ctrl_quats = (const float*)d_in[2];
    const int*   Nptr       = (const int*)d_in[3];

    int M = in_sizes[0];
    int K = in_sizes[1] / 3;

    float* out = (float*)d_out;

    if (K <= CAP) {
        int pblocks = (K + TPB - 1) / TPB;
        precompute_records<<<pblocks, TPB>>>(ctrl_trans, ctrl_quats, K);
        int blocks = (M + TPB - 1) / TPB;
        camera_spline_kernel<<<blocks, TPB>>>(t, Nptr, out, M, K);
    } else {
        int blocks = (M + TPB - 1) / TPB;
        camera_spline_kernel_direct<<<blocks, TPB>>>(t, ctrl_trans, ctrl_quats, Nptr, out, M, K);
    }
}